// round 14
// baseline (speedup 1.0000x reference)
#include <cuda_runtime.h>
#include <math.h>
#include <stdint.h>

#define BB   4
#define TT   2048
#define DD   1024
#define HH   16
#define DHD  64
#define MM   (BB * TT)        /* 8192 */
#define N3   (3 * DD)         /* 3072 */
#define NBH  (BB * HH)        /* 64   */

// ---------------------------------------------------------------------------
// Scratch (device globals; no dynamic allocation allowed)
// ---------------------------------------------------------------------------
__device__ float g_QKV[(size_t)MM * N3];          // [m][3072]
__device__ float g_Qt [(size_t)NBH * DHD * TT];   // [bh][d][t]
__device__ float g_Kt [(size_t)NBH * DHD * TT];   // [bh][d][t]
__device__ float g_V  [(size_t)NBH * TT * DHD];   // [bh][t][d]
__device__ float g_A  [(size_t)MM * DD];          // attn out, [m][n]
__device__ float g_cos[TT * 32];
__device__ float g_sin[TT * 32];

typedef unsigned long long u64;

// ---------------------------------------------------------------------------
// f32x2 packed-FMA helpers (SIMT attention kernel)
// ---------------------------------------------------------------------------
__device__ __forceinline__ u64 pack2(float x, float y) {
    u64 r; asm("mov.b64 %0, {%1, %2};" : "=l"(r) : "f"(x), "f"(y)); return r;
}
__device__ __forceinline__ float2 unpack2(u64 v) {
    float2 r; asm("mov.b64 {%0, %1}, %2;" : "=f"(r.x), "=f"(r.y) : "l"(v)); return r;
}
__device__ __forceinline__ u64 fma2(u64 a, u64 b, u64 c) {
    u64 d; asm("fma.rn.f32x2 %0, %1, %2, %3;" : "=l"(d) : "l"(a), "l"(b), "l"(c)); return d;
}
__device__ __forceinline__ u64 mul2(u64 a, u64 b) {
    u64 d; asm("mul.rn.f32x2 %0, %1, %2;" : "=l"(d) : "l"(a), "l"(b)); return d;
}

// ---------------------------------------------------------------------------
// tf32 mma.sync helpers (baseline sm_80+ ISA; works on target sm_103)
// ---------------------------------------------------------------------------
__device__ __forceinline__ uint32_t tf32r(float x) {
    uint32_t r; asm("cvt.rna.tf32.f32 %0, %1;" : "=r"(r) : "f"(x)); return r;
}
__device__ __forceinline__ void mma_tf32(float* d,
    uint32_t a0, uint32_t a1, uint32_t a2, uint32_t a3,
    uint32_t b0, uint32_t b1)
{
    asm volatile(
        "mma.sync.aligned.m16n8k8.row.col.f32.tf32.tf32.f32 "
        "{%0,%1,%2,%3}, {%4,%5,%6,%7}, {%8,%9}, {%0,%1,%2,%3};"
        : "+f"(d[0]), "+f"(d[1]), "+f"(d[2]), "+f"(d[3])
        : "r"(a0), "r"(a1), "r"(a2), "r"(a3), "r"(b0), "r"(b1));
}

// ---------------------------------------------------------------------------
// Kernel 1: RoPE cos/sin table (accurate sincos of the f32-rounded angle).
// ---------------------------------------------------------------------------
__global__ void rope_table_kernel() {
    int idx = blockIdx.x * blockDim.x + threadIdx.x;   // t*32 + i
    if (idx >= TT * 32) return;
    int t = idx >> 5, i = idx & 31;
    float inv = (float)pow(10000.0, -(double)i / 32.0);
    float ang = (float)t * inv;                        // f32 product like reference
    double s, c;
    sincos((double)ang, &s, &c);
    g_cos[idx] = (float)c;
    g_sin[idx] = (float)s;
}

// ---------------------------------------------------------------------------
// Kernel 2/5: 3xTF32 tensor-core GEMM  C[M][N] = A[M][1024] @ W[N][1024]^T + b
// 128x128 CTA tile, 256 threads = 8 warps (2m x 4n), warp tile 64x32.
// Smem holds FRAGMENT-PACKED hi/lo tf32 tiles (k-chunk = 32):
//   Ahi words [0,4096): ((ks*8+mt)*32+lane)*4 + slot, slot order [a0,a2,a1,a3]
//   Alo words [4096,8192)
//   Bhi words [8192,12288): ((ks*16+nt)*32+lane)*2 + {b0,b1}
//   Blo words [12288,16384)
// Consumers fetch whole fragments with LDS.128 / LDS.64 (conflict-free).
// 3 MMA passes: ahi*bhi + ahi*blo + alo*bhi  (error ~1e-6 vs ~5e-4 plain tf32)
// ---------------------------------------------------------------------------
#define GEMM_SMEM (65536)

__global__ __launch_bounds__(256, 2) void gemm_tc_kernel(
    const float* __restrict__ A, const float* __restrict__ W,
    const float* __restrict__ bias, float* __restrict__ C, int N)
{
    extern __shared__ uint32_t gsm[];

    const int tid  = threadIdx.x;
    const int lane = tid & 31;
    const int w    = tid >> 5;
    const int wm   = w & 1;          // 2 warps along m
    const int wn   = w >> 1;         // 4 warps along n
    const int m0 = blockIdx.y * 128;
    const int n0 = blockIdx.x * 128;

    const int row = tid >> 1;        // 0..127 (producer row)
    const int kb  = (tid & 1) * 8;   // producer k-octet base (0 or 8)

    const float* Arow = A + (size_t)(m0 + row) * 1024;
    const float* Wrow = W + (size_t)(n0 + row) * 1024;

    float acc[4][4][4];
    #pragma unroll
    for (int i = 0; i < 4; i++)
        #pragma unroll
        for (int j = 0; j < 4; j++)
            #pragma unroll
            for (int r = 0; r < 4; r++) acc[i][j][r] = 0.f;

    for (int kt = 0; kt < 32; kt++) {
        const int K0 = kt * 32;

        // ---- producer: load 8 k-floats per octet for A row and W row ----
        float va[2][8], vw[2][8];
        #pragma unroll
        for (int oct = 0; oct < 2; oct++) {
            int koff = kb + oct * 16;                  // ks = koff>>3
            float4 x0 = *(const float4*)(Arow + K0 + koff);
            float4 x1 = *(const float4*)(Arow + K0 + koff + 4);
            va[oct][0] = x0.x; va[oct][1] = x0.y; va[oct][2] = x0.z; va[oct][3] = x0.w;
            va[oct][4] = x1.x; va[oct][5] = x1.y; va[oct][6] = x1.z; va[oct][7] = x1.w;
            float4 y0 = *(const float4*)(Wrow + K0 + koff);
            float4 y1 = *(const float4*)(Wrow + K0 + koff + 4);
            vw[oct][0] = y0.x; vw[oct][1] = y0.y; vw[oct][2] = y0.z; vw[oct][3] = y0.w;
            vw[oct][4] = y1.x; vw[oct][5] = y1.y; vw[oct][6] = y1.z; vw[oct][7] = y1.w;
        }

        __syncthreads();   // previous chunk fully consumed

        // ---- producer: split hi/lo and store fragment-packed ----
        #pragma unroll
        for (int oct = 0; oct < 2; oct++) {
            const int ks = (kb + oct * 16) >> 3;       // 0..3
            // A fragments
            const int mt = row >> 4, r = row & 15;
            const int p0 = (r >> 3) & 1;               // slot pair (0,1) or (2,3)
            const uint32_t abase = (uint32_t)(((ks * 8 + mt) * 32 + (r & 7) * 4) * 4 + p0 * 2);
            #pragma unroll
            for (int j = 0; j < 4; j++) {
                float v0 = va[oct][j], v1 = va[oct][j + 4];
                uint32_t h0 = tf32r(v0), h1 = tf32r(v1);
                *(uint2*)&gsm[abase + j * 4] = make_uint2(h0, h1);
                float l0 = v0 - __uint_as_float(h0);
                float l1 = v1 - __uint_as_float(h1);
                *(uint2*)&gsm[4096 + abase + j * 4] = make_uint2(tf32r(l0), tf32r(l1));
            }
            // B fragments
            const int nt = row >> 3, r8 = row & 7;
            const uint32_t bbase = (uint32_t)(8192 + ((ks * 16 + nt) * 32 + r8 * 4) * 2);
            #pragma unroll
            for (int j = 0; j < 4; j++) {
                float v0 = vw[oct][j], v1 = vw[oct][j + 4];
                uint32_t h0 = tf32r(v0), h1 = tf32r(v1);
                *(uint2*)&gsm[bbase + j * 2] = make_uint2(h0, h1);
                float l0 = v0 - __uint_as_float(h0);
                float l1 = v1 - __uint_as_float(h1);
                *(uint2*)&gsm[4096 + bbase + j * 2] = make_uint2(tf32r(l0), tf32r(l1));
            }
        }
        __syncthreads();

        // ---- consumer: 4 k-steps x (16 tiles x 3 mma passes) per warp ----
        #pragma unroll
        for (int ks = 0; ks < 4; ks++) {
            uint4 ah[4], al[4];
            uint2 bh[4], bl[4];
            #pragma unroll
            for (int mtl = 0; mtl < 4; mtl++) {
                uint32_t ix = (uint32_t)(((ks * 8 + wm * 4 + mtl) * 32 + lane) * 4);
                ah[mtl] = *(const uint4*)&gsm[ix];
                al[mtl] = *(const uint4*)&gsm[4096 + ix];
            }
            #pragma unroll
            for (int ntl = 0; ntl < 4; ntl++) {
                uint32_t jx = (uint32_t)(8192 + ((ks * 16 + wn * 4 + ntl) * 32 + lane) * 2);
                bh[ntl] = *(const uint2*)&gsm[jx];
                bl[ntl] = *(const uint2*)&gsm[4096 + jx];
            }
            #pragma unroll
            for (int mtl = 0; mtl < 4; mtl++)
                #pragma unroll
                for (int ntl = 0; ntl < 4; ntl++) {
                    // stored slot order [a0,a2,a1,a3] -> operands {x,z,y,w}
                    mma_tf32(acc[mtl][ntl],
                             ah[mtl].x, ah[mtl].z, ah[mtl].y, ah[mtl].w,
                             bh[ntl].x, bh[ntl].y);
                    mma_tf32(acc[mtl][ntl],
                             ah[mtl].x, ah[mtl].z, ah[mtl].y, ah[mtl].w,
                             bl[ntl].x, bl[ntl].y);
                    mma_tf32(acc[mtl][ntl],
                             al[mtl].x, al[mtl].z, al[mtl].y, al[mtl].w,
                             bh[ntl].x, bh[ntl].y);
                }
        }
    }

    // ---- epilogue: write C with bias ----
    const int g  = lane >> 2;       // row within 16-tile (0..7)
    const int tg = lane & 3;        // col pair (0..3)
    #pragma unroll
    for (int mtl = 0; mtl < 4; mtl++) {
        int m = m0 + wm * 64 + mtl * 16 + g;
        #pragma unroll
        for (int ntl = 0; ntl < 4; ntl++) {
            int n = n0 + wn * 32 + ntl * 8 + 2 * tg;
            float2 bv = *(const float2*)&bias[n];
            float* c = acc[mtl][ntl];
            *(float2*)&C[(size_t)m * N + n] =
                make_float2(c[0] + bv.x, c[1] + bv.y);
            *(float2*)&C[(size_t)(m + 8) * N + n] =
                make_float2(c[2] + bv.x, c[3] + bv.y);
        }
    }
}

// ---------------------------------------------------------------------------
// Kernel 3: RoPE + scatter. Writes Q,K transposed [bh][d][t], V as [bh][t][d].
// ---------------------------------------------------------------------------
__global__ __launch_bounds__(256) void rope_scatter_kernel() {
    int idx = blockIdx.x * 256 + threadIdx.x;   // [0, MM*512)
    int m = idx >> 9;
    int p = idx & 511;
    int h = p >> 5, i = p & 31;
    int b = m >> 11, t = m & 2047;

    const float* base = g_QKV + (size_t)m * N3;
    float2 q = *(const float2*)&base[h * 64 + 2 * i];
    float2 k = *(const float2*)&base[1024 + h * 64 + 2 * i];
    float2 v = *(const float2*)&base[2048 + h * 64 + 2 * i];

    float c = g_cos[t * 32 + i];
    float s = g_sin[t * 32 + i];

    float qr0 = q.x * c - q.y * s, qr1 = q.x * s + q.y * c;
    float kr0 = k.x * c - k.y * s, kr1 = k.x * s + k.y * c;

    int bh = b * 16 + h;
    size_t toff = ((size_t)bh * 64 + 2 * i) * 2048 + t;
    g_Qt[toff]        = qr0;
    g_Qt[toff + 2048] = qr1;
    g_Kt[toff]        = kr0;
    g_Kt[toff + 2048] = kr1;

    *(float2*)&g_V[((size_t)bh * 2048 + t) * 64 + 2 * i] = v;
}

// ---------------------------------------------------------------------------
// Kernel 4: flash attention (SIMT f32x2; unchanged from R11 passing version).
// ---------------------------------------------------------------------------
#define ATTN_SMEM ((8192 + 4096 + 4096 + 8192) * 4)   /* 98304 B */

__global__ __launch_bounds__(256, 2) void attn_kernel() {
    extern __shared__ float sm[];
    float* Qs = sm;              // [d][q]  64x128 (pre-scaled by 1/8)
    float* Ks = Qs + 8192;       // [d][k]  64x64
    float* Vs = Ks + 4096;       // [k][d]  64x64
    float* Ps = Vs + 4096;       // [k][q]  64x128, 16B-chunk swizzled

    const int bh = blockIdx.y;
    const int q0 = blockIdx.x * 128;
    const int tid = threadIdx.x;
    const int tx = tid & 15;
    const int ty = tid >> 4;

    const float* Qb = g_Qt + (size_t)bh * 64 * 2048;
    const float* Kb = g_Kt + (size_t)bh * 64 * 2048;
    const float* Vb = g_V  + (size_t)bh * 2048 * 64;

    #pragma unroll
    for (int it = 0; it < 8; it++) {
        int idx = tid + it * 256;
        int d = idx >> 5, qq = (idx & 31) * 4;
        float4 v = *(const float4*)&Qb[(size_t)d * 2048 + q0 + qq];
        v.x *= 0.125f; v.y *= 0.125f; v.z *= 0.125f; v.w *= 0.125f;
        *(float4*)&Qs[d * 128 + qq] = v;
    }

    float m_i[8], l_i[8];
    u64 o2[4][4];
    #pragma unroll
    for (int r = 0; r < 8; r++) { m_i[r] = -1e30f; l_i[r] = 0.f; }
    #pragma unroll
    for (int mp = 0; mp < 4; mp++)
        #pragma unroll
        for (int j = 0; j < 4; j++) o2[mp][j] = 0ULL;

    for (int kt = 0; kt < 32; kt++) {
        __syncthreads();
        #pragma unroll
        for (int it = 0; it < 4; it++) {
            int idx = tid + it * 256;
            int d = idx >> 4, kq = (idx & 15) * 4;
            *(float4*)&Ks[d * 64 + kq] =
                *(const float4*)&Kb[(size_t)d * 2048 + kt * 64 + kq];
            *(float4*)&Vs[idx * 4] =
                *(const float4*)&Vb[(size_t)kt * 4096 + idx * 4];
        }
        __syncthreads();

        u64 s2[4][4];
        #pragma unroll
        for (int mp = 0; mp < 4; mp++)
            #pragma unroll
            for (int j = 0; j < 4; j++) s2[mp][j] = 0ULL;

        #pragma unroll 4
        for (int d = 0; d < 64; d++) {
            const float* qrow = &Qs[d * 128 + 8 * ty];
            u64 q01 = *(const u64*)(qrow);
            u64 q23 = *(const u64*)(qrow + 2);
            u64 q45 = *(const u64*)(qrow + 4);
            u64 q67 = *(const u64*)(qrow + 6);
            float4 kv = *(const float4*)&Ks[d * 64 + 4 * tx];
            u64 k0 = pack2(kv.x, kv.x);
            u64 k1 = pack2(kv.y, kv.y);
            u64 k2 = pack2(kv.z, kv.z);
            u64 k3 = pack2(kv.w, kv.w);
            s2[0][0] = fma2(q01, k0, s2[0][0]); s2[0][1] = fma2(q01, k1, s2[0][1]);
            s2[0][2] = fma2(q01, k2, s2[0][2]); s2[0][3] = fma2(q01, k3, s2[0][3]);
            s2[1][0] = fma2(q23, k0, s2[1][0]); s2[1][1] = fma2(q23, k1, s2[1][1]);
            s2[1][2] = fma2(q23, k2, s2[1][2]); s2[1][3] = fma2(q23, k3, s2[1][3]);
            s2[2][0] = fma2(q45, k0, s2[2][0]); s2[2][1] = fma2(q45, k1, s2[2][1]);
            s2[2][2] = fma2(q45, k2, s2[2][2]); s2[2][3] = fma2(q45, k3, s2[2][3]);
            s2[3][0] = fma2(q67, k0, s2[3][0]); s2[3][1] = fma2(q67, k1, s2[3][1]);
            s2[3][2] = fma2(q67, k2, s2[3][2]); s2[3][3] = fma2(q67, k3, s2[3][3]);
        }

        float s[8][4];
        #pragma unroll
        for (int mp = 0; mp < 4; mp++)
            #pragma unroll
            for (int j = 0; j < 4; j++) {
                float2 u = unpack2(s2[mp][j]);
                s[2 * mp][j] = u.x; s[2 * mp + 1][j] = u.y;
            }

        float alpha[8];
        #pragma unroll
        for (int r = 0; r < 8; r++) {
            float mx = fmaxf(fmaxf(s[r][0], s[r][1]), fmaxf(s[r][2], s[r][3]));
            #pragma unroll
            for (int off = 1; off < 16; off <<= 1)
                mx = fmaxf(mx, __shfl_xor_sync(0xffffffffu, mx, off));
            float mnew = fmaxf(m_i[r], mx);
            alpha[r] = __expf(m_i[r] - mnew);
            float rsum = 0.f;
            #pragma unroll
            for (int j = 0; j < 4; j++) {
                s[r][j] = __expf(s[r][j] - mnew);
                rsum += s[r][j];
            }
            #pragma unroll
            for (int off = 1; off < 16; off <<= 1)
                rsum += __shfl_xor_sync(0xffffffffu, rsum, off);
            l_i[r] = l_i[r] * alpha[r] + rsum;
            m_i[r] = mnew;
        }
        #pragma unroll
        for (int mp = 0; mp < 4; mp++) {
            u64 al2 = pack2(alpha[2 * mp], alpha[2 * mp + 1]);
            #pragma unroll
            for (int j = 0; j < 4; j++) o2[mp][j] = mul2(o2[mp][j], al2);
        }

        #pragma unroll
        for (int j = 0; j < 4; j++) {
            int k = 4 * tx + j;
            int x = (k >> 1) & 7;
            int cA = ((2 * ty) ^ x) << 2;
            float* prow = &Ps[k * 128];
            *(float4*)(prow + cA) =
                make_float4(s[0][j], s[1][j], s[2][j], s[3][j]);
            *(float4*)(prow + (cA ^ 4)) =
                make_float4(s[4][j], s[5][j], s[6][j], s[7][j]);
        }
        __syncthreads();

        #pragma unroll 4
        for (int k = 0; k < 64; k++) {
            int x = (k >> 1) & 7;
            int cA = ((2 * ty) ^ x) << 2;
            const float* prow = &Ps[k * 128];
            u64 p01 = *(const u64*)(prow + cA);
            u64 p23 = *(const u64*)(prow + cA + 2);
            u64 p45 = *(const u64*)(prow + (cA ^ 4));
            u64 p67 = *(const u64*)(prow + (cA ^ 4) + 2);
            float4 vv = *(const float4*)&Vs[k * 64 + 4 * tx];
            u64 v0 = pack2(vv.x, vv.x);
            u64 v1 = pack2(vv.y, vv.y);
            u64 v2 = pack2(vv.z, vv.z);
            u64 v3 = pack2(vv.w, vv.w);
            o2[0][0] = fma2(p01, v0, o2[0][0]); o2[0][1] = fma2(p01, v1, o2[0][1]);
            o2[0][2] = fma2(p01, v2, o2[0][2]); o2[0][3] = fma2(p01, v3, o2[0][3]);
            o2[1][0] = fma2(p23, v0, o2[1][0]); o2[1][1] = fma2(p23, v1, o2[1][1]);
            o2[1][2] = fma2(p23, v2, o2[1][2]); o2[1][3] = fma2(p23, v3, o2[1][3]);
            o2[2][0] = fma2(p45, v0, o2[2][0]); o2[2][1] = fma2(p45, v1, o2[2][1]);
            o2[2][2] = fma2(p45, v2, o2[2][2]); o2[2][3] = fma2(p45, v3, o2[2][3]);
            o2[3][0] = fma2(p67, v0, o2[3][0]); o2[3][1] = fma2(p67, v1, o2[3][1]);
            o2[3][2] = fma2(p67, v2, o2[3][2]); o2[3][3] = fma2(p67, v3, o2[3][3]);
        }
    }

    const int b = bh >> 4, h = bh & 15;
    #pragma unroll
    for (int mp = 0; mp < 4; mp++) {
        float2 u0 = unpack2(o2[mp][0]);
        float2 u1 = unpack2(o2[mp][1]);
        float2 u2 = unpack2(o2[mp][2]);
        float2 u3 = unpack2(o2[mp][3]);
        float inv0 = 1.0f / l_i[2 * mp];
        float inv1 = 1.0f / l_i[2 * mp + 1];
        size_t r0 = ((size_t)(b * 2048 + q0 + 8 * ty + 2 * mp)) * 1024 + h * 64 + 4 * tx;
        *(float4*)&g_A[r0] =
            make_float4(u0.x * inv0, u1.x * inv0, u2.x * inv0, u3.x * inv0);
        *(float4*)&g_A[r0 + 1024] =
            make_float4(u0.y * inv1, u1.y * inv1, u2.y * inv1, u3.y * inv1);
    }
}

// ---------------------------------------------------------------------------
// Launcher
// ---------------------------------------------------------------------------
extern "C" void kernel_launch(void* const* d_in, const int* in_sizes, int n_in,
                              void* d_out, int out_size) {
    (void)in_sizes; (void)n_in; (void)out_size;
    const float* query = (const float*)d_in[0];
    const float* w_in  = (const float*)d_in[1];
    const float* b_in  = (const float*)d_in[2];
    const float* w_out = (const float*)d_in[3];
    const float* b_out = (const float*)d_in[4];
    float* out = (float*)d_out;

    void* pQKV = nullptr; void* pA = nullptr;
    cudaGetSymbolAddress(&pQKV, g_QKV);
    cudaGetSymbolAddress(&pA,   g_A);
    cudaFuncSetAttribute(attn_kernel,
                         cudaFuncAttributeMaxDynamicSharedMemorySize, ATTN_SMEM);
    cudaFuncSetAttribute(gemm_tc_kernel,
                         cudaFuncAttributeMaxDynamicSharedMemorySize, GEMM_SMEM);

    rope_table_kernel<<<(TT * 32 + 255) / 256, 256>>>();

    gemm_tc_kernel<<<dim3(N3 / 128, MM / 128), 256, GEMM_SMEM>>>(
        query, w_in, b_in, (float*)pQKV, N3);

    rope_scatter_kernel<<<(MM * 512) / 256, 256>>>();

    attn_kernel<<<dim3(TT / 128, NBH), 256, ATTN_SMEM>>>();

    gemm_tc_kernel<<<dim3(DD / 128, MM / 128), 256, GEMM_SMEM>>>(
        (const float*)pA, w_out, b_out, out, DD);
}

// round 15
// speedup vs baseline: 1.0337x; 1.0337x over previous
#include <cuda_runtime.h>
#include <math.h>
#include <stdint.h>

#define BB   4
#define TT   2048
#define DD   1024
#define HH   16
#define DHD  64
#define MM   (BB * TT)        /* 8192 */
#define N3   (3 * DD)         /* 3072 */
#define NBH  (BB * HH)        /* 64   */

// ---------------------------------------------------------------------------
// Scratch (device globals; no dynamic allocation allowed)
// ---------------------------------------------------------------------------
__device__ float g_Qt [(size_t)NBH * DHD * TT];   // [bh][d][t]
__device__ float g_Kt [(size_t)NBH * DHD * TT];   // [bh][d][t]
__device__ float g_V  [(size_t)NBH * TT * DHD];   // [bh][t][d]
__device__ float g_A  [(size_t)MM * DD];          // attn out, [m][n]
__device__ float g_cos[TT * 32];
__device__ float g_sin[TT * 32];

typedef unsigned long long u64;

// ---------------------------------------------------------------------------
// f32x2 packed-FMA helpers (SIMT attention kernel)
// ---------------------------------------------------------------------------
__device__ __forceinline__ u64 pack2(float x, float y) {
    u64 r; asm("mov.b64 %0, {%1, %2};" : "=l"(r) : "f"(x), "f"(y)); return r;
}
__device__ __forceinline__ float2 unpack2(u64 v) {
    float2 r; asm("mov.b64 {%0, %1}, %2;" : "=f"(r.x), "=f"(r.y) : "l"(v)); return r;
}
__device__ __forceinline__ u64 fma2(u64 a, u64 b, u64 c) {
    u64 d; asm("fma.rn.f32x2 %0, %1, %2, %3;" : "=l"(d) : "l"(a), "l"(b), "l"(c)); return d;
}
__device__ __forceinline__ u64 mul2(u64 a, u64 b) {
    u64 d; asm("mul.rn.f32x2 %0, %1, %2;" : "=l"(d) : "l"(a), "l"(b)); return d;
}

// ---------------------------------------------------------------------------
// tf32 mma.sync helpers (baseline sm_80+ ISA; compiles for target sm_103)
// ---------------------------------------------------------------------------
__device__ __forceinline__ void mma_tf32(float* d,
    uint32_t a0, uint32_t a1, uint32_t a2, uint32_t a3,
    uint32_t b0, uint32_t b1)
{
    asm volatile(
        "mma.sync.aligned.m16n8k8.row.col.f32.tf32.tf32.f32 "
        "{%0,%1,%2,%3}, {%4,%5,%6,%7}, {%8,%9}, {%0,%1,%2,%3};"
        : "+f"(d[0]), "+f"(d[1]), "+f"(d[2]), "+f"(d[3])
        : "r"(a0), "r"(a1), "r"(a2), "r"(a3), "r"(b0), "r"(b1));
}
// Mask-based tf32 hi/lo split: 1 LOP3 (alu pipe) + 1 FADD (fma pipe) per value.
// HMMA.tf32 ignores the low mantissa bits of the operand register, so no cvt.
__device__ __forceinline__ void split_tf32(float v, uint32_t& hi, uint32_t& lo) {
    uint32_t h = __float_as_uint(v) & 0xffffe000u;
    hi = h;
    lo = __float_as_uint(v - __uint_as_float(h));
}

// ---------------------------------------------------------------------------
// Kernel 1: RoPE cos/sin table (accurate sincos of the f32-rounded angle).
// ---------------------------------------------------------------------------
__global__ void rope_table_kernel() {
    int idx = blockIdx.x * blockDim.x + threadIdx.x;   // t*32 + i
    if (idx >= TT * 32) return;
    int t = idx >> 5, i = idx & 31;
    float inv = (float)pow(10000.0, -(double)i / 32.0);
    float ang = (float)t * inv;                        // f32 product like reference
    double s, c;
    sincos((double)ang, &s, &c);
    g_cos[idx] = (float)c;
    g_sin[idx] = (float)s;
}

// ---------------------------------------------------------------------------
// Kernel 2/4: 3xTF32 tensor-core GEMM  C[M][N] = A[M][1024] @ W[N][1024]^T + b
// 128x128 CTA tile, 256 threads = 8 warps (2m x 4n), warp tile 64x32.
// Fragment-packed hi/lo smem (see R14); producer split is now LOP3+FADD.
// mode 0: write C + bias.
// mode 1 (QKV): apply bias + RoPE in registers, scatter to g_Qt/g_Kt/g_V.
// ---------------------------------------------------------------------------
#define GEMM_SMEM (65536)

__global__ __launch_bounds__(256, 2) void gemm_tc_kernel(
    const float* __restrict__ A, const float* __restrict__ W,
    const float* __restrict__ bias, float* __restrict__ C, int N, int mode)
{
    extern __shared__ uint32_t gsm[];

    const int tid  = threadIdx.x;
    const int lane = tid & 31;
    const int w    = tid >> 5;
    const int wm   = w & 1;          // 2 warps along m
    const int wn   = w >> 1;         // 4 warps along n
    const int m0 = blockIdx.y * 128;
    const int n0 = blockIdx.x * 128;

    const int row = tid >> 1;        // 0..127 (producer row)
    const int kb  = (tid & 1) * 8;   // producer k-octet base (0 or 8)

    const float* Arow = A + (size_t)(m0 + row) * 1024;
    const float* Wrow = W + (size_t)(n0 + row) * 1024;

    float acc[4][4][4];
    #pragma unroll
    for (int i = 0; i < 4; i++)
        #pragma unroll
        for (int j = 0; j < 4; j++)
            #pragma unroll
            for (int r = 0; r < 4; r++) acc[i][j][r] = 0.f;

    for (int kt = 0; kt < 32; kt++) {
        const int K0 = kt * 32;

        // ---- producer: load 8 k-floats per octet for A row and W row ----
        float va[2][8], vw[2][8];
        #pragma unroll
        for (int oct = 0; oct < 2; oct++) {
            int koff = kb + oct * 16;
            float4 x0 = *(const float4*)(Arow + K0 + koff);
            float4 x1 = *(const float4*)(Arow + K0 + koff + 4);
            va[oct][0] = x0.x; va[oct][1] = x0.y; va[oct][2] = x0.z; va[oct][3] = x0.w;
            va[oct][4] = x1.x; va[oct][5] = x1.y; va[oct][6] = x1.z; va[oct][7] = x1.w;
            float4 y0 = *(const float4*)(Wrow + K0 + koff);
            float4 y1 = *(const float4*)(Wrow + K0 + koff + 4);
            vw[oct][0] = y0.x; vw[oct][1] = y0.y; vw[oct][2] = y0.z; vw[oct][3] = y0.w;
            vw[oct][4] = y1.x; vw[oct][5] = y1.y; vw[oct][6] = y1.z; vw[oct][7] = y1.w;
        }

        __syncthreads();   // previous chunk fully consumed

        // ---- producer: mask-split hi/lo and store fragment-packed ----
        #pragma unroll
        for (int oct = 0; oct < 2; oct++) {
            const int ks = (kb + oct * 16) >> 3;       // 0..3
            const int mt = row >> 4, r = row & 15;
            const int p0 = (r >> 3) & 1;
            const uint32_t abase = (uint32_t)(((ks * 8 + mt) * 32 + (r & 7) * 4) * 4 + p0 * 2);
            #pragma unroll
            for (int j = 0; j < 4; j++) {
                uint32_t h0, l0, h1, l1;
                split_tf32(va[oct][j],     h0, l0);
                split_tf32(va[oct][j + 4], h1, l1);
                *(uint2*)&gsm[abase + j * 4]        = make_uint2(h0, h1);
                *(uint2*)&gsm[4096 + abase + j * 4] = make_uint2(l0, l1);
            }
            const int nt = row >> 3, r8 = row & 7;
            const uint32_t bbase = (uint32_t)(8192 + ((ks * 16 + nt) * 32 + r8 * 4) * 2);
            #pragma unroll
            for (int j = 0; j < 4; j++) {
                uint32_t h0, l0, h1, l1;
                split_tf32(vw[oct][j],     h0, l0);
                split_tf32(vw[oct][j + 4], h1, l1);
                *(uint2*)&gsm[bbase + j * 2]        = make_uint2(h0, h1);
                *(uint2*)&gsm[4096 + bbase + j * 2] = make_uint2(l0, l1);
            }
        }
        __syncthreads();

        // ---- consumer: 4 k-steps x (16 tiles x 3 mma passes) per warp ----
        #pragma unroll
        for (int ks = 0; ks < 4; ks++) {
            uint4 ah[4], al[4];
            uint2 bh[4], bl[4];
            #pragma unroll
            for (int mtl = 0; mtl < 4; mtl++) {
                uint32_t ix = (uint32_t)(((ks * 8 + wm * 4 + mtl) * 32 + lane) * 4);
                ah[mtl] = *(const uint4*)&gsm[ix];
                al[mtl] = *(const uint4*)&gsm[4096 + ix];
            }
            #pragma unroll
            for (int ntl = 0; ntl < 4; ntl++) {
                uint32_t jx = (uint32_t)(8192 + ((ks * 16 + wn * 4 + ntl) * 32 + lane) * 2);
                bh[ntl] = *(const uint2*)&gsm[jx];
                bl[ntl] = *(const uint2*)&gsm[4096 + jx];
            }
            #pragma unroll
            for (int mtl = 0; mtl < 4; mtl++)
                #pragma unroll
                for (int ntl = 0; ntl < 4; ntl++) {
                    mma_tf32(acc[mtl][ntl],
                             ah[mtl].x, ah[mtl].z, ah[mtl].y, ah[mtl].w,
                             bh[ntl].x, bh[ntl].y);
                    mma_tf32(acc[mtl][ntl],
                             ah[mtl].x, ah[mtl].z, ah[mtl].y, ah[mtl].w,
                             bl[ntl].x, bl[ntl].y);
                    mma_tf32(acc[mtl][ntl],
                             al[mtl].x, al[mtl].z, al[mtl].y, al[mtl].w,
                             bh[ntl].x, bh[ntl].y);
                }
        }
    }

    // ---- epilogue ----
    const int g  = lane >> 2;       // row within 16-tile (0..7)
    const int tg = lane & 3;        // col pair (0..3)

    if (mode == 0) {
        #pragma unroll
        for (int mtl = 0; mtl < 4; mtl++) {
            int m = m0 + wm * 64 + mtl * 16 + g;
            #pragma unroll
            for (int ntl = 0; ntl < 4; ntl++) {
                int n = n0 + wn * 32 + ntl * 8 + 2 * tg;
                float2 bv = *(const float2*)&bias[n];
                float* c = acc[mtl][ntl];
                *(float2*)&C[(size_t)m * N + n] =
                    make_float2(c[0] + bv.x, c[1] + bv.y);
                *(float2*)&C[(size_t)(m + 8) * N + n] =
                    make_float2(c[2] + bv.x, c[3] + bv.y);
            }
        }
        return;
    }

    // mode 1: fused bias + RoPE + scatter (n pairs are rotary pairs: n even)
    #pragma unroll
    for (int mtl = 0; mtl < 4; mtl++) {
        int m = m0 + wm * 64 + mtl * 16 + g;     // rows m and m+8, same batch
        int b = m >> 11;
        int t = m & 2047;                        // t and t+8 (no b crossing)
        #pragma unroll
        for (int ntl = 0; ntl < 4; ntl++) {
            int n = n0 + wn * 32 + ntl * 8 + 2 * tg;
            float2 bv = *(const float2*)&bias[n];
            float* c = acc[mtl][ntl];
            float v0 = c[0] + bv.x, v1 = c[1] + bv.y;   // row m
            float v2 = c[2] + bv.x, v3 = c[3] + bv.y;   // row m+8
            int region = n >> 10;                // 0=Q 1=K 2=V
            int nn = n & 1023;
            int h  = nn >> 6;
            int i2 = nn & 63;                    // 2*i
            int bh = b * 16 + h;
            if (region < 2) {
                int ci = (i2 >> 1);
                float c0 = g_cos[t * 32 + ci],        s0 = g_sin[t * 32 + ci];
                float c1 = g_cos[(t + 8) * 32 + ci],  s1 = g_sin[(t + 8) * 32 + ci];
                float* dst = region ? g_Kt : g_Qt;
                size_t off = ((size_t)bh * 64 + i2) * 2048 + t;
                dst[off]            = v0 * c0 - v1 * s0;
                dst[off + 2048]     = v0 * s0 + v1 * c0;
                dst[off + 8]        = v2 * c1 - v3 * s1;
                dst[off + 2048 + 8] = v2 * s1 + v3 * c1;
            } else {
                size_t off = ((size_t)bh * 2048 + t) * 64 + i2;
                *(float2*)&g_V[off]            = make_float2(v0, v1);
                *(float2*)&g_V[off + 8 * 64]   = make_float2(v2, v3);
            }
        }
    }
}

// ---------------------------------------------------------------------------
// Kernel 3: flash attention (SIMT f32x2; unchanged from R11 passing version).
// ---------------------------------------------------------------------------
#define ATTN_SMEM ((8192 + 4096 + 4096 + 8192) * 4)   /* 98304 B */

__global__ __launch_bounds__(256, 2) void attn_kernel() {
    extern __shared__ float sm[];
    float* Qs = sm;              // [d][q]  64x128 (pre-scaled by 1/8)
    float* Ks = Qs + 8192;       // [d][k]  64x64
    float* Vs = Ks + 4096;       // [k][d]  64x64
    float* Ps = Vs + 4096;       // [k][q]  64x128, 16B-chunk swizzled

    const int bh = blockIdx.y;
    const int q0 = blockIdx.x * 128;
    const int tid = threadIdx.x;
    const int tx = tid & 15;
    const int ty = tid >> 4;

    const float* Qb = g_Qt + (size_t)bh * 64 * 2048;
    const float* Kb = g_Kt + (size_t)bh * 64 * 2048;
    const float* Vb = g_V  + (size_t)bh * 2048 * 64;

    #pragma unroll
    for (int it = 0; it < 8; it++) {
        int idx = tid + it * 256;
        int d = idx >> 5, qq = (idx & 31) * 4;
        float4 v = *(const float4*)&Qb[(size_t)d * 2048 + q0 + qq];
        v.x *= 0.125f; v.y *= 0.125f; v.z *= 0.125f; v.w *= 0.125f;
        *(float4*)&Qs[d * 128 + qq] = v;
    }

    float m_i[8], l_i[8];
    u64 o2[4][4];
    #pragma unroll
    for (int r = 0; r < 8; r++) { m_i[r] = -1e30f; l_i[r] = 0.f; }
    #pragma unroll
    for (int mp = 0; mp < 4; mp++)
        #pragma unroll
        for (int j = 0; j < 4; j++) o2[mp][j] = 0ULL;

    for (int kt = 0; kt < 32; kt++) {
        __syncthreads();
        #pragma unroll
        for (int it = 0; it < 4; it++) {
            int idx = tid + it * 256;
            int d = idx >> 4, kq = (idx & 15) * 4;
            *(float4*)&Ks[d * 64 + kq] =
                *(const float4*)&Kb[(size_t)d * 2048 + kt * 64 + kq];
            *(float4*)&Vs[idx * 4] =
                *(const float4*)&Vb[(size_t)kt * 4096 + idx * 4];
        }
        __syncthreads();

        u64 s2[4][4];
        #pragma unroll
        for (int mp = 0; mp < 4; mp++)
            #pragma unroll
            for (int j = 0; j < 4; j++) s2[mp][j] = 0ULL;

        #pragma unroll 4
        for (int d = 0; d < 64; d++) {
            const float* qrow = &Qs[d * 128 + 8 * ty];
            u64 q01 = *(const u64*)(qrow);
            u64 q23 = *(const u64*)(qrow + 2);
            u64 q45 = *(const u64*)(qrow + 4);
            u64 q67 = *(const u64*)(qrow + 6);
            float4 kv = *(const float4*)&Ks[d * 64 + 4 * tx];
            u64 k0 = pack2(kv.x, kv.x);
            u64 k1 = pack2(kv.y, kv.y);
            u64 k2 = pack2(kv.z, kv.z);
            u64 k3 = pack2(kv.w, kv.w);
            s2[0][0] = fma2(q01, k0, s2[0][0]); s2[0][1] = fma2(q01, k1, s2[0][1]);
            s2[0][2] = fma2(q01, k2, s2[0][2]); s2[0][3] = fma2(q01, k3, s2[0][3]);
            s2[1][0] = fma2(q23, k0, s2[1][0]); s2[1][1] = fma2(q23, k1, s2[1][1]);
            s2[1][2] = fma2(q23, k2, s2[1][2]); s2[1][3] = fma2(q23, k3, s2[1][3]);
            s2[2][0] = fma2(q45, k0, s2[2][0]); s2[2][1] = fma2(q45, k1, s2[2][1]);
            s2[2][2] = fma2(q45, k2, s2[2][2]); s2[2][3] = fma2(q45, k3, s2[2][3]);
            s2[3][0] = fma2(q67, k0, s2[3][0]); s2[3][1] = fma2(q67, k1, s2[3][1]);
            s2[3][2] = fma2(q67, k2, s2[3][2]); s2[3][3] = fma2(q67, k3, s2[3][3]);
        }

        float s[8][4];
        #pragma unroll
        for (int mp = 0; mp < 4; mp++)
            #pragma unroll
            for (int j = 0; j < 4; j++) {
                float2 u = unpack2(s2[mp][j]);
                s[2 * mp][j] = u.x; s[2 * mp + 1][j] = u.y;
            }

        float alpha[8];
        #pragma unroll
        for (int r = 0; r < 8; r++) {
            float mx = fmaxf(fmaxf(s[r][0], s[r][1]), fmaxf(s[r][2], s[r][3]));
            #pragma unroll
            for (int off = 1; off < 16; off <<= 1)
                mx = fmaxf(mx, __shfl_xor_sync(0xffffffffu, mx, off));
            float mnew = fmaxf(m_i[r], mx);
            alpha[r] = __expf(m_i[r] - mnew);
            float rsum = 0.f;
            #pragma unroll
            for (int j = 0; j < 4; j++) {
                s[r][j] = __expf(s[r][j] - mnew);
                rsum += s[r][j];
            }
            #pragma unroll
            for (int off = 1; off < 16; off <<= 1)
                rsum += __shfl_xor_sync(0xffffffffu, rsum, off);
            l_i[r] = l_i[r] * alpha[r] + rsum;
            m_i[r] = mnew;
        }
        #pragma unroll
        for (int mp = 0; mp < 4; mp++) {
            u64 al2 = pack2(alpha[2 * mp], alpha[2 * mp + 1]);
            #pragma unroll
            for (int j = 0; j < 4; j++) o2[mp][j] = mul2(o2[mp][j], al2);
        }

        #pragma unroll
        for (int j = 0; j < 4; j++) {
            int k = 4 * tx + j;
            int x = (k >> 1) & 7;
            int cA = ((2 * ty) ^ x) << 2;
            float* prow = &Ps[k * 128];
            *(float4*)(prow + cA) =
                make_float4(s[0][j], s[1][j], s[2][j], s[3][j]);
            *(float4*)(prow + (cA ^ 4)) =
                make_float4(s[4][j], s[5][j], s[6][j], s[7][j]);
        }
        __syncthreads();

        #pragma unroll 4
        for (int k = 0; k < 64; k++) {
            int x = (k >> 1) & 7;
            int cA = ((2 * ty) ^ x) << 2;
            const float* prow = &Ps[k * 128];
            u64 p01 = *(const u64*)(prow + cA);
            u64 p23 = *(const u64*)(prow + cA + 2);
            u64 p45 = *(const u64*)(prow + (cA ^ 4));
            u64 p67 = *(const u64*)(prow + (cA ^ 4) + 2);
            float4 vv = *(const float4*)&Vs[k * 64 + 4 * tx];
            u64 v0 = pack2(vv.x, vv.x);
            u64 v1 = pack2(vv.y, vv.y);
            u64 v2 = pack2(vv.z, vv.z);
            u64 v3 = pack2(vv.w, vv.w);
            o2[0][0] = fma2(p01, v0, o2[0][0]); o2[0][1] = fma2(p01, v1, o2[0][1]);
            o2[0][2] = fma2(p01, v2, o2[0][2]); o2[0][3] = fma2(p01, v3, o2[0][3]);
            o2[1][0] = fma2(p23, v0, o2[1][0]); o2[1][1] = fma2(p23, v1, o2[1][1]);
            o2[1][2] = fma2(p23, v2, o2[1][2]); o2[1][3] = fma2(p23, v3, o2[1][3]);
            o2[2][0] = fma2(p45, v0, o2[2][0]); o2[2][1] = fma2(p45, v1, o2[2][1]);
            o2[2][2] = fma2(p45, v2, o2[2][2]); o2[2][3] = fma2(p45, v3, o2[2][3]);
            o2[3][0] = fma2(p67, v0, o2[3][0]); o2[3][1] = fma2(p67, v1, o2[3][1]);
            o2[3][2] = fma2(p67, v2, o2[3][2]); o2[3][3] = fma2(p67, v3, o2[3][3]);
        }
    }

    const int b = bh >> 4, h = bh & 15;
    #pragma unroll
    for (int mp = 0; mp < 4; mp++) {
        float2 u0 = unpack2(o2[mp][0]);
        float2 u1 = unpack2(o2[mp][1]);
        float2 u2 = unpack2(o2[mp][2]);
        float2 u3 = unpack2(o2[mp][3]);
        float inv0 = 1.0f / l_i[2 * mp];
        float inv1 = 1.0f / l_i[2 * mp + 1];
        size_t r0 = ((size_t)(b * 2048 + q0 + 8 * ty + 2 * mp)) * 1024 + h * 64 + 4 * tx;
        *(float4*)&g_A[r0] =
            make_float4(u0.x * inv0, u1.x * inv0, u2.x * inv0, u3.x * inv0);
        *(float4*)&g_A[r0 + 1024] =
            make_float4(u0.y * inv1, u1.y * inv1, u2.y * inv1, u3.y * inv1);
    }
}

// ---------------------------------------------------------------------------
// Launcher
// ---------------------------------------------------------------------------
extern "C" void kernel_launch(void* const* d_in, const int* in_sizes, int n_in,
                              void* d_out, int out_size) {
    (void)in_sizes; (void)n_in; (void)out_size;
    const float* query = (const float*)d_in[0];
    const float* w_in  = (const float*)d_in[1];
    const float* b_in  = (const float*)d_in[2];
    const float* w_out = (const float*)d_in[3];
    const float* b_out = (const float*)d_in[4];
    float* out = (float*)d_out;

    void* pA = nullptr;
    cudaGetSymbolAddress(&pA, g_A);
    cudaFuncSetAttribute(attn_kernel,
                         cudaFuncAttributeMaxDynamicSharedMemorySize, ATTN_SMEM);
    cudaFuncSetAttribute(gemm_tc_kernel,
                         cudaFuncAttributeMaxDynamicSharedMemorySize, GEMM_SMEM);

    rope_table_kernel<<<(TT * 32 + 255) / 256, 256>>>();

    // QKV projection with fused bias + RoPE + scatter epilogue
    gemm_tc_kernel<<<dim3(N3 / 128, MM / 128), 256, GEMM_SMEM>>>(
        query, w_in, b_in, nullptr, N3, 1);

    attn_kernel<<<dim3(TT / 128, NBH), 256, ATTN_SMEM>>>();

    // output projection
    gemm_tc_kernel<<<dim3(DD / 128, MM / 128), 256, GEMM_SMEM>>>(
        (const float*)pA, w_out, b_out, out, DD, 0);
}

// round 16
// speedup vs baseline: 1.3237x; 1.2805x over previous
#include <cuda_runtime.h>
#include <math.h>
#include <stdint.h>

#define BB   4
#define TT   2048
#define DD   1024
#define HH   16
#define DHD  64
#define MM   (BB * TT)        /* 8192 */
#define N3   (3 * DD)         /* 3072 */
#define NBH  (BB * HH)        /* 64   */

// ---------------------------------------------------------------------------
// Scratch (device globals; no dynamic allocation allowed)
// ---------------------------------------------------------------------------
__device__ float g_Qt [(size_t)NBH * DHD * TT];   // [bh][d][t]
__device__ float g_Kt [(size_t)NBH * DHD * TT];   // [bh][d][t]
__device__ float g_V  [(size_t)NBH * TT * DHD];   // [bh][t][d]
__device__ float g_A  [(size_t)MM * DD];          // attn out, [m][n]
__device__ float g_cos[TT * 32];
__device__ float g_sin[TT * 32];

typedef unsigned long long u64;

// ---------------------------------------------------------------------------
// f32x2 packed-FMA helpers (SIMT attention kernel)
// ---------------------------------------------------------------------------
__device__ __forceinline__ u64 pack2(float x, float y) {
    u64 r; asm("mov.b64 %0, {%1, %2};" : "=l"(r) : "f"(x), "f"(y)); return r;
}
__device__ __forceinline__ float2 unpack2(u64 v) {
    float2 r; asm("mov.b64 {%0, %1}, %2;" : "=f"(r.x), "=f"(r.y) : "l"(v)); return r;
}
__device__ __forceinline__ u64 fma2(u64 a, u64 b, u64 c) {
    u64 d; asm("fma.rn.f32x2 %0, %1, %2, %3;" : "=l"(d) : "l"(a), "l"(b), "l"(c)); return d;
}
__device__ __forceinline__ u64 mul2(u64 a, u64 b) {
    u64 d; asm("mul.rn.f32x2 %0, %1, %2;" : "=l"(d) : "l"(a), "l"(b)); return d;
}

// ---------------------------------------------------------------------------
// bf16 mma.sync helpers (baseline sm_80+ ISA; compiles for target sm_103)
// ---------------------------------------------------------------------------
__device__ __forceinline__ uint32_t smem_u32(const void* p) {
    uint32_t a;
    asm("{ .reg .u64 t; cvta.to.shared.u64 t, %1; cvt.u32.u64 %0, t; }" : "=r"(a) : "l"(p));
    return a;
}
// pack two floats to bf16x2 (round-to-nearest): low half = first arg
__device__ __forceinline__ uint32_t bf16x2_rn(float lo, float hi) {
    uint32_t d; asm("cvt.rn.bf16x2.f32 %0, %1, %2;" : "=r"(d) : "f"(hi), "f"(lo)); return d;
}
__device__ __forceinline__ void ldsm4(uint32_t* r, uint32_t addr) {
    asm volatile("ldmatrix.sync.aligned.m8n8.x4.shared.b16 {%0,%1,%2,%3}, [%4];"
        : "=r"(r[0]), "=r"(r[1]), "=r"(r[2]), "=r"(r[3]) : "r"(addr));
}
__device__ __forceinline__ void mma_bf16(float* d,
    uint32_t a0, uint32_t a1, uint32_t a2, uint32_t a3, uint32_t b0, uint32_t b1)
{
    asm volatile(
        "mma.sync.aligned.m16n8k16.row.col.f32.bf16.bf16.f32 "
        "{%0,%1,%2,%3}, {%4,%5,%6,%7}, {%8,%9}, {%0,%1,%2,%3};"
        : "+f"(d[0]), "+f"(d[1]), "+f"(d[2]), "+f"(d[3])
        : "r"(a0), "r"(a1), "r"(a2), "r"(a3), "r"(b0), "r"(b1));
}

// ---------------------------------------------------------------------------
// Kernel 1: RoPE cos/sin table (accurate sincos of the f32-rounded angle).
// ---------------------------------------------------------------------------
__global__ void rope_table_kernel() {
    int idx = blockIdx.x * blockDim.x + threadIdx.x;   // t*32 + i
    if (idx >= TT * 32) return;
    int t = idx >> 5, i = idx & 31;
    float inv = (float)pow(10000.0, -(double)i / 32.0);
    float ang = (float)t * inv;                        // f32 product like reference
    double s, c;
    sincos((double)ang, &s, &c);
    g_cos[idx] = (float)c;
    g_sin[idx] = (float)s;
}

// ---------------------------------------------------------------------------
// Kernel 2/4: 3-pass split-bf16 tensor GEMM  C[M][N]=A[M][1024]@W[N][1024]^T+b
// 128x128 CTA tile, 256 thr = 8 warps (2m x 4n), warp tile 64x32, k-chunk 32.
// Smem per buffer (40960 B): A_hi rows [0), A_lo [+10240), B_hi [+20480),
// B_lo [+30720); each 128 rows x 32 bf16, row padded to 80 B (conflict-free
// STS.128 stores AND ldmatrix loads: 5n mod 8 is a bijection).
// Double buffered (81920 B total), one __syncthreads per chunk; LDG prefetch
// issued before the MMA block. 3 passes: hh + hl + lh (rounded split).
// mode 0: write C + bias.   mode 1 (QKV): fused bias + RoPE + scatter.
// ---------------------------------------------------------------------------
#define GEMM_SMEM (81920)

__global__ __launch_bounds__(256, 2) void gemm_tc_kernel(
    const float* __restrict__ A, const float* __restrict__ W,
    const float* __restrict__ bias, float* __restrict__ C, int N, int mode)
{
    extern __shared__ char gsmc[];
    const uint32_t smb = smem_u32(gsmc);

    const int tid  = threadIdx.x;
    const int lane = tid & 31;
    const int w    = tid >> 5;
    const int wm   = w & 1;          // 2 warps along m
    const int wn   = w >> 1;         // 4 warps along n
    const int m0 = blockIdx.y * 128;
    const int n0 = blockIdx.x * 128;

    // producer: tid 0-127 -> A row tid; tid 128-255 -> B row tid-128
    const bool isB = (tid >= 128);
    const int  prow = isB ? (tid - 128) : tid;
    const float* __restrict__ src = isB ? (W + (size_t)(n0 + prow) * 1024)
                                        : (A + (size_t)(m0 + prow) * 1024);
    const uint32_t prowoff = (isB ? 20480u : 0u) + (uint32_t)prow * 80u;

    float acc[4][4][4];
    #pragma unroll
    for (int i = 0; i < 4; i++)
        #pragma unroll
        for (int j = 0; j < 4; j++)
            #pragma unroll
            for (int r = 0; r < 4; r++) acc[i][j][r] = 0.f;

    float f[32];

    // ---- prologue: chunk 0 -> buffer 0 ----
    #pragma unroll
    for (int q = 0; q < 8; q++) {
        float4 v = *(const float4*)(src + q * 4);
        f[4*q] = v.x; f[4*q+1] = v.y; f[4*q+2] = v.z; f[4*q+3] = v.w;
    }
    {
        char* dst = gsmc + prowoff;
        #pragma unroll
        for (int q = 0; q < 4; q++) {
            uint32_t hw[4], lw[4];
            #pragma unroll
            for (int p = 0; p < 4; p++) {
                float x0 = f[8*q + 2*p], x1 = f[8*q + 2*p + 1];
                uint32_t h = bf16x2_rn(x0, x1);
                float h0 = __uint_as_float(h << 16);
                float h1 = __uint_as_float(h & 0xffff0000u);
                hw[p] = h;
                lw[p] = bf16x2_rn(x0 - h0, x1 - h1);
            }
            *(uint4*)(dst + q * 16)         = make_uint4(hw[0], hw[1], hw[2], hw[3]);
            *(uint4*)(dst + 10240 + q * 16) = make_uint4(lw[0], lw[1], lw[2], lw[3]);
        }
    }
    __syncthreads();

    // fragment address components (consumer)
    const uint32_t arow_l = (uint32_t)(wm * 64 + (lane & 15));
    const uint32_t acol_l = (uint32_t)(((lane >> 4) & 1) * 16);
    const uint32_t brow_l = (uint32_t)(wn * 32 + ((lane >> 4) & 1) * 8 + (lane & 7));
    const uint32_t bcol_l = (uint32_t)(((lane >> 3) & 1) * 16);

    for (int kt = 0; kt < 32; kt++) {
        const uint32_t sb = smb + (uint32_t)(kt & 1) * 40960u;

        if (kt < 31) {   // prefetch next chunk into registers (hidden by MMAs)
            const float* s2 = src + (kt + 1) * 32;
            #pragma unroll
            for (int q = 0; q < 8; q++) {
                float4 v = *(const float4*)(s2 + q * 4);
                f[4*q] = v.x; f[4*q+1] = v.y; f[4*q+2] = v.z; f[4*q+3] = v.w;
            }
        }

        // ---- consume current buffer ----
        #pragma unroll
        for (int ks = 0; ks < 2; ks++) {
            uint32_t bh[8], bl[8];
            #pragma unroll
            for (int ntp = 0; ntp < 2; ntp++) {
                uint32_t ba = sb + 20480u + (brow_l + ntp * 16) * 80u
                            + (uint32_t)(ks * 32) + bcol_l;
                ldsm4(&bh[ntp * 4], ba);
                ldsm4(&bl[ntp * 4], ba + 10240u);
            }
            #pragma unroll
            for (int mtl = 0; mtl < 4; mtl++) {
                uint32_t aa = sb + (arow_l + mtl * 16) * 80u
                            + (uint32_t)(ks * 32) + acol_l;
                uint32_t ah[4], al[4];
                ldsm4(ah, aa);
                ldsm4(al, aa + 10240u);
                #pragma unroll
                for (int ntl = 0; ntl < 4; ntl++) {
                    mma_bf16(acc[mtl][ntl], ah[0], ah[1], ah[2], ah[3],
                             bh[ntl*2], bh[ntl*2+1]);
                    mma_bf16(acc[mtl][ntl], ah[0], ah[1], ah[2], ah[3],
                             bl[ntl*2], bl[ntl*2+1]);
                    mma_bf16(acc[mtl][ntl], al[0], al[1], al[2], al[3],
                             bh[ntl*2], bh[ntl*2+1]);
                }
            }
        }

        if (kt < 31) {   // split + store next chunk into the other buffer
            char* dst = gsmc + (uint32_t)((kt + 1) & 1) * 40960u + prowoff;
            #pragma unroll
            for (int q = 0; q < 4; q++) {
                uint32_t hw[4], lw[4];
                #pragma unroll
                for (int p = 0; p < 4; p++) {
                    float x0 = f[8*q + 2*p], x1 = f[8*q + 2*p + 1];
                    uint32_t h = bf16x2_rn(x0, x1);
                    float h0 = __uint_as_float(h << 16);
                    float h1 = __uint_as_float(h & 0xffff0000u);
                    hw[p] = h;
                    lw[p] = bf16x2_rn(x0 - h0, x1 - h1);
                }
                *(uint4*)(dst + q * 16)         = make_uint4(hw[0], hw[1], hw[2], hw[3]);
                *(uint4*)(dst + 10240 + q * 16) = make_uint4(lw[0], lw[1], lw[2], lw[3]);
            }
        }
        __syncthreads();
    }

    // ---- epilogue ----
    const int g  = lane >> 2;       // row within 16-tile (0..7)
    const int tg = lane & 3;        // col pair (0..3)

    if (mode == 0) {
        #pragma unroll
        for (int mtl = 0; mtl < 4; mtl++) {
            int m = m0 + wm * 64 + mtl * 16 + g;
            #pragma unroll
            for (int ntl = 0; ntl < 4; ntl++) {
                int n = n0 + wn * 32 + ntl * 8 + 2 * tg;
                float2 bv = *(const float2*)&bias[n];
                float* c = acc[mtl][ntl];
                *(float2*)&C[(size_t)m * N + n] =
                    make_float2(c[0] + bv.x, c[1] + bv.y);
                *(float2*)&C[(size_t)(m + 8) * N + n] =
                    make_float2(c[2] + bv.x, c[3] + bv.y);
            }
        }
        return;
    }

    // mode 1: fused bias + RoPE + scatter (n pairs are rotary pairs: n even)
    #pragma unroll
    for (int mtl = 0; mtl < 4; mtl++) {
        int m = m0 + wm * 64 + mtl * 16 + g;     // rows m and m+8, same batch
        int b = m >> 11;
        int t = m & 2047;                        // t and t+8 (no b crossing)
        #pragma unroll
        for (int ntl = 0; ntl < 4; ntl++) {
            int n = n0 + wn * 32 + ntl * 8 + 2 * tg;
            float2 bv = *(const float2*)&bias[n];
            float* c = acc[mtl][ntl];
            float v0 = c[0] + bv.x, v1 = c[1] + bv.y;   // row m
            float v2 = c[2] + bv.x, v3 = c[3] + bv.y;   // row m+8
            int region = n >> 10;                // 0=Q 1=K 2=V
            int nn = n & 1023;
            int h  = nn >> 6;
            int i2 = nn & 63;                    // 2*i
            int bh = b * 16 + h;
            if (region < 2) {
                int ci = (i2 >> 1);
                float c0 = g_cos[t * 32 + ci],        s0 = g_sin[t * 32 + ci];
                float c1 = g_cos[(t + 8) * 32 + ci],  s1 = g_sin[(t + 8) * 32 + ci];
                float* dst = region ? g_Kt : g_Qt;
                size_t off = ((size_t)bh * 64 + i2) * 2048 + t;
                dst[off]            = v0 * c0 - v1 * s0;
                dst[off + 2048]     = v0 * s0 + v1 * c0;
                dst[off + 8]        = v2 * c1 - v3 * s1;
                dst[off + 2048 + 8] = v2 * s1 + v3 * c1;
            } else {
                size_t off = ((size_t)bh * 2048 + t) * 64 + i2;
                *(float2*)&g_V[off]            = make_float2(v0, v1);
                *(float2*)&g_V[off + 8 * 64]   = make_float2(v2, v3);
            }
        }
    }
}

// ---------------------------------------------------------------------------
// Kernel 3: flash attention (SIMT f32x2; unchanged passing version).
// ---------------------------------------------------------------------------
#define ATTN_SMEM ((8192 + 4096 + 4096 + 8192) * 4)   /* 98304 B */

__global__ __launch_bounds__(256, 2) void attn_kernel() {
    extern __shared__ float sm[];
    float* Qs = sm;              // [d][q]  64x128 (pre-scaled by 1/8)
    float* Ks = Qs + 8192;       // [d][k]  64x64
    float* Vs = Ks + 4096;       // [k][d]  64x64
    float* Ps = Vs + 4096;       // [k][q]  64x128, 16B-chunk swizzled

    const int bh = blockIdx.y;
    const int q0 = blockIdx.x * 128;
    const int tid = threadIdx.x;
    const int tx = tid & 15;
    const int ty = tid >> 4;

    const float* Qb = g_Qt + (size_t)bh * 64 * 2048;
    const float* Kb = g_Kt + (size_t)bh * 64 * 2048;
    const float* Vb = g_V  + (size_t)bh * 2048 * 64;

    #pragma unroll
    for (int it = 0; it < 8; it++) {
        int idx = tid + it * 256;
        int d = idx >> 5, qq = (idx & 31) * 4;
        float4 v = *(const float4*)&Qb[(size_t)d * 2048 + q0 + qq];
        v.x *= 0.125f; v.y *= 0.125f; v.z *= 0.125f; v.w *= 0.125f;
        *(float4*)&Qs[d * 128 + qq] = v;
    }

    float m_i[8], l_i[8];
    u64 o2[4][4];
    #pragma unroll
    for (int r = 0; r < 8; r++) { m_i[r] = -1e30f; l_i[r] = 0.f; }
    #pragma unroll
    for (int mp = 0; mp < 4; mp++)
        #pragma unroll
        for (int j = 0; j < 4; j++) o2[mp][j] = 0ULL;

    for (int kt = 0; kt < 32; kt++) {
        __syncthreads();
        #pragma unroll
        for (int it = 0; it < 4; it++) {
            int idx = tid + it * 256;
            int d = idx >> 4, kq = (idx & 15) * 4;
            *(float4*)&Ks[d * 64 + kq] =
                *(const float4*)&Kb[(size_t)d * 2048 + kt * 64 + kq];
            *(float4*)&Vs[idx * 4] =
                *(const float4*)&Vb[(size_t)kt * 4096 + idx * 4];
        }
        __syncthreads();

        u64 s2[4][4];
        #pragma unroll
        for (int mp = 0; mp < 4; mp++)
            #pragma unroll
            for (int j = 0; j < 4; j++) s2[mp][j] = 0ULL;

        #pragma unroll 4
        for (int d = 0; d < 64; d++) {
            const float* qrow = &Qs[d * 128 + 8 * ty];
            u64 q01 = *(const u64*)(qrow);
            u64 q23 = *(const u64*)(qrow + 2);
            u64 q45 = *(const u64*)(qrow + 4);
            u64 q67 = *(const u64*)(qrow + 6);
            float4 kv = *(const float4*)&Ks[d * 64 + 4 * tx];
            u64 k0 = pack2(kv.x, kv.x);
            u64 k1 = pack2(kv.y, kv.y);
            u64 k2 = pack2(kv.z, kv.z);
            u64 k3 = pack2(kv.w, kv.w);
            s2[0][0] = fma2(q01, k0, s2[0][0]); s2[0][1] = fma2(q01, k1, s2[0][1]);
            s2[0][2] = fma2(q01, k2, s2[0][2]); s2[0][3] = fma2(q01, k3, s2[0][3]);
            s2[1][0] = fma2(q23, k0, s2[1][0]); s2[1][1] = fma2(q23, k1, s2[1][1]);
            s2[1][2] = fma2(q23, k2, s2[1][2]); s2[1][3] = fma2(q23, k3, s2[1][3]);
            s2[2][0] = fma2(q45, k0, s2[2][0]); s2[2][1] = fma2(q45, k1, s2[2][1]);
            s2[2][2] = fma2(q45, k2, s2[2][2]); s2[2][3] = fma2(q45, k3, s2[2][3]);
            s2[3][0] = fma2(q67, k0, s2[3][0]); s2[3][1] = fma2(q67, k1, s2[3][1]);
            s2[3][2] = fma2(q67, k2, s2[3][2]); s2[3][3] = fma2(q67, k3, s2[3][3]);
        }

        float s[8][4];
        #pragma unroll
        for (int mp = 0; mp < 4; mp++)
            #pragma unroll
            for (int j = 0; j < 4; j++) {
                float2 u = unpack2(s2[mp][j]);
                s[2 * mp][j] = u.x; s[2 * mp + 1][j] = u.y;
            }

        float alpha[8];
        #pragma unroll
        for (int r = 0; r < 8; r++) {
            float mx = fmaxf(fmaxf(s[r][0], s[r][1]), fmaxf(s[r][2], s[r][3]));
            #pragma unroll
            for (int off = 1; off < 16; off <<= 1)
                mx = fmaxf(mx, __shfl_xor_sync(0xffffffffu, mx, off));
            float mnew = fmaxf(m_i[r], mx);
            alpha[r] = __expf(m_i[r] - mnew);
            float rsum = 0.f;
            #pragma unroll
            for (int j = 0; j < 4; j++) {
                s[r][j] = __expf(s[r][j] - mnew);
                rsum += s[r][j];
            }
            #pragma unroll
            for (int off = 1; off < 16; off <<= 1)
                rsum += __shfl_xor_sync(0xffffffffu, rsum, off);
            l_i[r] = l_i[r] * alpha[r] + rsum;
            m_i[r] = mnew;
        }
        #pragma unroll
        for (int mp = 0; mp < 4; mp++) {
            u64 al2 = pack2(alpha[2 * mp], alpha[2 * mp + 1]);
            #pragma unroll
            for (int j = 0; j < 4; j++) o2[mp][j] = mul2(o2[mp][j], al2);
        }

        #pragma unroll
        for (int j = 0; j < 4; j++) {
            int k = 4 * tx + j;
            int x = (k >> 1) & 7;
            int cA = ((2 * ty) ^ x) << 2;
            float* prow = &Ps[k * 128];
            *(float4*)(prow + cA) =
                make_float4(s[0][j], s[1][j], s[2][j], s[3][j]);
            *(float4*)(prow + (cA ^ 4)) =
                make_float4(s[4][j], s[5][j], s[6][j], s[7][j]);
        }
        __syncthreads();

        #pragma unroll 4
        for (int k = 0; k < 64; k++) {
            int x = (k >> 1) & 7;
            int cA = ((2 * ty) ^ x) << 2;
            const float* prow = &Ps[k * 128];
            u64 p01 = *(const u64*)(prow + cA);
            u64 p23 = *(const u64*)(prow + cA + 2);
            u64 p45 = *(const u64*)(prow + (cA ^ 4));
            u64 p67 = *(const u64*)(prow + (cA ^ 4) + 2);
            float4 vv = *(const float4*)&Vs[k * 64 + 4 * tx];
            u64 v0 = pack2(vv.x, vv.x);
            u64 v1 = pack2(vv.y, vv.y);
            u64 v2 = pack2(vv.z, vv.z);
            u64 v3 = pack2(vv.w, vv.w);
            o2[0][0] = fma2(p01, v0, o2[0][0]); o2[0][1] = fma2(p01, v1, o2[0][1]);
            o2[0][2] = fma2(p01, v2, o2[0][2]); o2[0][3] = fma2(p01, v3, o2[0][3]);
            o2[1][0] = fma2(p23, v0, o2[1][0]); o2[1][1] = fma2(p23, v1, o2[1][1]);
            o2[1][2] = fma2(p23, v2, o2[1][2]); o2[1][3] = fma2(p23, v3, o2[1][3]);
            o2[2][0] = fma2(p45, v0, o2[2][0]); o2[2][1] = fma2(p45, v1, o2[2][1]);
            o2[2][2] = fma2(p45, v2, o2[2][2]); o2[2][3] = fma2(p45, v3, o2[2][3]);
            o2[3][0] = fma2(p67, v0, o2[3][0]); o2[3][1] = fma2(p67, v1, o2[3][1]);
            o2[3][2] = fma2(p67, v2, o2[3][2]); o2[3][3] = fma2(p67, v3, o2[3][3]);
        }
    }

    const int b = bh >> 4, h = bh & 15;
    #pragma unroll
    for (int mp = 0; mp < 4; mp++) {
        float2 u0 = unpack2(o2[mp][0]);
        float2 u1 = unpack2(o2[mp][1]);
        float2 u2 = unpack2(o2[mp][2]);
        float2 u3 = unpack2(o2[mp][3]);
        float inv0 = 1.0f / l_i[2 * mp];
        float inv1 = 1.0f / l_i[2 * mp + 1];
        size_t r0 = ((size_t)(b * 2048 + q0 + 8 * ty + 2 * mp)) * 1024 + h * 64 + 4 * tx;
        *(float4*)&g_A[r0] =
            make_float4(u0.x * inv0, u1.x * inv0, u2.x * inv0, u3.x * inv0);
        *(float4*)&g_A[r0 + 1024] =
            make_float4(u0.y * inv1, u1.y * inv1, u2.y * inv1, u3.y * inv1);
    }
}

// ---------------------------------------------------------------------------
// Launcher
// ---------------------------------------------------------------------------
extern "C" void kernel_launch(void* const* d_in, const int* in_sizes, int n_in,
                              void* d_out, int out_size) {
    (void)in_sizes; (void)n_in; (void)out_size;
    const float* query = (const float*)d_in[0];
    const float* w_in  = (const float*)d_in[1];
    const float* b_in  = (const float*)d_in[2];
    const float* w_out = (const float*)d_in[3];
    const float* b_out = (const float*)d_in[4];
    float* out = (float*)d_out;

    void* pA = nullptr;
    cudaGetSymbolAddress(&pA, g_A);
    cudaFuncSetAttribute(attn_kernel,
                         cudaFuncAttributeMaxDynamicSharedMemorySize, ATTN_SMEM);
    cudaFuncSetAttribute(gemm_tc_kernel,
                         cudaFuncAttributeMaxDynamicSharedMemorySize, GEMM_SMEM);

    rope_table_kernel<<<(TT * 32 + 255) / 256, 256>>>();

    // QKV projection with fused bias + RoPE + scatter epilogue
    gemm_tc_kernel<<<dim3(N3 / 128, MM / 128), 256, GEMM_SMEM>>>(
        query, w_in, b_in, nullptr, N3, 1);

    attn_kernel<<<dim3(TT / 128, NBH), 256, ATTN_SMEM>>>();

    // output projection
    gemm_tc_kernel<<<dim3(DD / 128, MM / 128), 256, GEMM_SMEM>>>(
        (const float*)pA, w_out, b_out, out, DD, 0);
}

// round 17
// speedup vs baseline: 2.5790x; 1.9484x over previous
#include <cuda_runtime.h>
#include <cuda_fp16.h>
#include <math.h>
#include <stdint.h>

#define BB   4
#define TT   2048
#define DD   1024
#define HH   16
#define DHD  64
#define MM   (BB * TT)        /* 8192 */
#define N3   (3 * DD)         /* 3072 */
#define NBH  (BB * HH)        /* 64   */

// ---------------------------------------------------------------------------
// Scratch (device globals; no dynamic allocation allowed)
// ---------------------------------------------------------------------------
__device__ __half g_Qh[(size_t)NBH * TT * DHD];   // [bh][t][d] fp16, pre-scaled 1/8
__device__ __half g_Kh[(size_t)NBH * TT * DHD];   // [bh][t][d] fp16
__device__ __half g_Vh[(size_t)NBH * TT * DHD];   // [bh][t][d] fp16
__device__ float  g_A [(size_t)MM * DD];          // attn out fp32, [m][n]
__device__ float  g_cos[TT * 32];
__device__ float  g_sin[TT * 32];

// ---------------------------------------------------------------------------
// helpers
// ---------------------------------------------------------------------------
__device__ __forceinline__ uint32_t smem_u32(const void* p) {
    uint32_t a;
    asm("{ .reg .u64 t; cvta.to.shared.u64 t, %1; cvt.u32.u64 %0, t; }" : "=r"(a) : "l"(p));
    return a;
}
// pack two floats to bf16x2 (rn): low half = first arg
__device__ __forceinline__ uint32_t bf16x2_rn(float lo, float hi) {
    uint32_t d; asm("cvt.rn.bf16x2.f32 %0, %1, %2;" : "=r"(d) : "f"(hi), "f"(lo)); return d;
}
// pack two floats to fp16x2 (rn): low half = first arg
__device__ __forceinline__ uint32_t h2_rn(float lo, float hi) {
    uint32_t d; asm("cvt.rn.f16x2.f32 %0, %1, %2;" : "=r"(d) : "f"(hi), "f"(lo)); return d;
}
__device__ __forceinline__ void ldsm4(uint32_t* r, uint32_t addr) {
    asm volatile("ldmatrix.sync.aligned.m8n8.x4.shared.b16 {%0,%1,%2,%3}, [%4];"
        : "=r"(r[0]), "=r"(r[1]), "=r"(r[2]), "=r"(r[3]) : "r"(addr));
}
__device__ __forceinline__ void ldsm4t(uint32_t* r, uint32_t addr) {
    asm volatile("ldmatrix.sync.aligned.m8n8.x4.trans.shared.b16 {%0,%1,%2,%3}, [%4];"
        : "=r"(r[0]), "=r"(r[1]), "=r"(r[2]), "=r"(r[3]) : "r"(addr));
}
__device__ __forceinline__ void mma_bf16(float* d,
    uint32_t a0, uint32_t a1, uint32_t a2, uint32_t a3, uint32_t b0, uint32_t b1)
{
    asm volatile(
        "mma.sync.aligned.m16n8k16.row.col.f32.bf16.bf16.f32 "
        "{%0,%1,%2,%3}, {%4,%5,%6,%7}, {%8,%9}, {%0,%1,%2,%3};"
        : "+f"(d[0]), "+f"(d[1]), "+f"(d[2]), "+f"(d[3])
        : "r"(a0), "r"(a1), "r"(a2), "r"(a3), "r"(b0), "r"(b1));
}
__device__ __forceinline__ void mma_f16(float* d,
    uint32_t a0, uint32_t a1, uint32_t a2, uint32_t a3, uint32_t b0, uint32_t b1)
{
    asm volatile(
        "mma.sync.aligned.m16n8k16.row.col.f32.f16.f16.f32 "
        "{%0,%1,%2,%3}, {%4,%5,%6,%7}, {%8,%9}, {%0,%1,%2,%3};"
        : "+f"(d[0]), "+f"(d[1]), "+f"(d[2]), "+f"(d[3])
        : "r"(a0), "r"(a1), "r"(a2), "r"(a3), "r"(b0), "r"(b1));
}

// ---------------------------------------------------------------------------
// Kernel 1: RoPE cos/sin table (accurate sincos of the f32-rounded angle).
// ---------------------------------------------------------------------------
__global__ void rope_table_kernel() {
    int idx = blockIdx.x * blockDim.x + threadIdx.x;   // t*32 + i
    if (idx >= TT * 32) return;
    int t = idx >> 5, i = idx & 31;
    float inv = (float)pow(10000.0, -(double)i / 32.0);
    float ang = (float)t * inv;                        // f32 product like reference
    double s, c;
    sincos((double)ang, &s, &c);
    g_cos[idx] = (float)c;
    g_sin[idx] = (float)s;
}

// ---------------------------------------------------------------------------
// Kernel 2/4: 3-pass split-bf16 tensor GEMM (unchanged from R16 passing).
// mode 0: write C + bias (fp32).
// mode 1 (QKV): fused bias + RoPE, write fp16 Q (x1/8), K, V to g_Qh/Kh/Vh.
// ---------------------------------------------------------------------------
#define GEMM_SMEM (81920)

__global__ __launch_bounds__(256, 2) void gemm_tc_kernel(
    const float* __restrict__ A, const float* __restrict__ W,
    const float* __restrict__ bias, float* __restrict__ C, int N, int mode)
{
    extern __shared__ char gsmc[];

    const int tid  = threadIdx.x;
    const int lane = tid & 31;
    const int w    = tid >> 5;
    const int wm   = w & 1;
    const int wn   = w >> 1;
    const int m0 = blockIdx.y * 128;
    const int n0 = blockIdx.x * 128;
    const uint32_t smb = smem_u32(gsmc);

    const bool isB = (tid >= 128);
    const int  prow = isB ? (tid - 128) : tid;
    const float* __restrict__ src = isB ? (W + (size_t)(n0 + prow) * 1024)
                                        : (A + (size_t)(m0 + prow) * 1024);
    const uint32_t prowoff = (isB ? 20480u : 0u) + (uint32_t)prow * 80u;

    float acc[4][4][4];
    #pragma unroll
    for (int i = 0; i < 4; i++)
        #pragma unroll
        for (int j = 0; j < 4; j++)
            #pragma unroll
            for (int r = 0; r < 4; r++) acc[i][j][r] = 0.f;

    float f[32];

    #pragma unroll
    for (int q = 0; q < 8; q++) {
        float4 v = *(const float4*)(src + q * 4);
        f[4*q] = v.x; f[4*q+1] = v.y; f[4*q+2] = v.z; f[4*q+3] = v.w;
    }
    {
        char* dst = gsmc + prowoff;
        #pragma unroll
        for (int q = 0; q < 4; q++) {
            uint32_t hw[4], lw[4];
            #pragma unroll
            for (int p = 0; p < 4; p++) {
                float x0 = f[8*q + 2*p], x1 = f[8*q + 2*p + 1];
                uint32_t h = bf16x2_rn(x0, x1);
                float h0 = __uint_as_float(h << 16);
                float h1 = __uint_as_float(h & 0xffff0000u);
                hw[p] = h;
                lw[p] = bf16x2_rn(x0 - h0, x1 - h1);
            }
            *(uint4*)(dst + q * 16)         = make_uint4(hw[0], hw[1], hw[2], hw[3]);
            *(uint4*)(dst + 10240 + q * 16) = make_uint4(lw[0], lw[1], lw[2], lw[3]);
        }
    }
    __syncthreads();

    const uint32_t arow_l = (uint32_t)(wm * 64 + (lane & 15));
    const uint32_t acol_l = (uint32_t)(((lane >> 4) & 1) * 16);
    const uint32_t brow_l = (uint32_t)(wn * 32 + ((lane >> 4) & 1) * 8 + (lane & 7));
    const uint32_t bcol_l = (uint32_t)(((lane >> 3) & 1) * 16);

    for (int kt = 0; kt < 32; kt++) {
        const uint32_t sb = smb + (uint32_t)(kt & 1) * 40960u;

        if (kt < 31) {
            const float* s2 = src + (kt + 1) * 32;
            #pragma unroll
            for (int q = 0; q < 8; q++) {
                float4 v = *(const float4*)(s2 + q * 4);
                f[4*q] = v.x; f[4*q+1] = v.y; f[4*q+2] = v.z; f[4*q+3] = v.w;
            }
        }

        #pragma unroll
        for (int ks = 0; ks < 2; ks++) {
            uint32_t bh[8], bl[8];
            #pragma unroll
            for (int ntp = 0; ntp < 2; ntp++) {
                uint32_t ba = sb + 20480u + (brow_l + ntp * 16) * 80u
                            + (uint32_t)(ks * 32) + bcol_l;
                ldsm4(&bh[ntp * 4], ba);
                ldsm4(&bl[ntp * 4], ba + 10240u);
            }
            #pragma unroll
            for (int mtl = 0; mtl < 4; mtl++) {
                uint32_t aa = sb + (arow_l + mtl * 16) * 80u
                            + (uint32_t)(ks * 32) + acol_l;
                uint32_t ah[4], al[4];
                ldsm4(ah, aa);
                ldsm4(al, aa + 10240u);
                #pragma unroll
                for (int ntl = 0; ntl < 4; ntl++) {
                    mma_bf16(acc[mtl][ntl], ah[0], ah[1], ah[2], ah[3],
                             bh[ntl*2], bh[ntl*2+1]);
                    mma_bf16(acc[mtl][ntl], ah[0], ah[1], ah[2], ah[3],
                             bl[ntl*2], bl[ntl*2+1]);
                    mma_bf16(acc[mtl][ntl], al[0], al[1], al[2], al[3],
                             bh[ntl*2], bh[ntl*2+1]);
                }
            }
        }

        if (kt < 31) {
            char* dst = gsmc + (uint32_t)((kt + 1) & 1) * 40960u + prowoff;
            #pragma unroll
            for (int q = 0; q < 4; q++) {
                uint32_t hw[4], lw[4];
                #pragma unroll
                for (int p = 0; p < 4; p++) {
                    float x0 = f[8*q + 2*p], x1 = f[8*q + 2*p + 1];
                    uint32_t h = bf16x2_rn(x0, x1);
                    float h0 = __uint_as_float(h << 16);
                    float h1 = __uint_as_float(h & 0xffff0000u);
                    hw[p] = h;
                    lw[p] = bf16x2_rn(x0 - h0, x1 - h1);
                }
                *(uint4*)(dst + q * 16)         = make_uint4(hw[0], hw[1], hw[2], hw[3]);
                *(uint4*)(dst + 10240 + q * 16) = make_uint4(lw[0], lw[1], lw[2], lw[3]);
            }
        }
        __syncthreads();
    }

    const int g  = lane >> 2;
    const int tg = lane & 3;

    if (mode == 0) {
        #pragma unroll
        for (int mtl = 0; mtl < 4; mtl++) {
            int m = m0 + wm * 64 + mtl * 16 + g;
            #pragma unroll
            for (int ntl = 0; ntl < 4; ntl++) {
                int n = n0 + wn * 32 + ntl * 8 + 2 * tg;
                float2 bv = *(const float2*)&bias[n];
                float* c = acc[mtl][ntl];
                *(float2*)&C[(size_t)m * N + n] =
                    make_float2(c[0] + bv.x, c[1] + bv.y);
                *(float2*)&C[(size_t)(m + 8) * N + n] =
                    make_float2(c[2] + bv.x, c[3] + bv.y);
            }
        }
        return;
    }

    // mode 1: fused bias + RoPE + fp16 scatter (n even -> rotary pairs)
    uint32_t* Qh32 = (uint32_t*)g_Qh;
    uint32_t* Kh32 = (uint32_t*)g_Kh;
    uint32_t* Vh32 = (uint32_t*)g_Vh;
    #pragma unroll
    for (int mtl = 0; mtl < 4; mtl++) {
        int m = m0 + wm * 64 + mtl * 16 + g;
        int b = m >> 11;
        int t = m & 2047;
        #pragma unroll
        for (int ntl = 0; ntl < 4; ntl++) {
            int n = n0 + wn * 32 + ntl * 8 + 2 * tg;
            float2 bv = *(const float2*)&bias[n];
            float* c = acc[mtl][ntl];
            float v0 = c[0] + bv.x, v1 = c[1] + bv.y;   // row m
            float v2 = c[2] + bv.x, v3 = c[3] + bv.y;   // row m+8
            int region = n >> 10;                // 0=Q 1=K 2=V
            int nn = n & 1023;
            int h  = nn >> 6;
            int i2 = nn & 63;                    // 2*i
            int bh = b * 16 + h;
            size_t off = (((size_t)bh * 2048 + t) * 64 + i2) >> 1;  // half2 index
            if (region < 2) {
                int ci = i2 >> 1;
                float c0 = g_cos[t * 32 + ci],        s0 = g_sin[t * 32 + ci];
                float c1 = g_cos[(t + 8) * 32 + ci],  s1 = g_sin[(t + 8) * 32 + ci];
                float r0 = v0 * c0 - v1 * s0, r1 = v0 * s0 + v1 * c0;
                float r2 = v2 * c1 - v3 * s1, r3 = v2 * s1 + v3 * c1;
                if (region == 0) {   // Q: fold softmax scale 1/8
                    Qh32[off]           = h2_rn(r0 * 0.125f, r1 * 0.125f);
                    Qh32[off + 8 * 32]  = h2_rn(r2 * 0.125f, r3 * 0.125f);
                } else {
                    Kh32[off]           = h2_rn(r0, r1);
                    Kh32[off + 8 * 32]  = h2_rn(r2, r3);
                }
            } else {
                Vh32[off]           = h2_rn(v0, v1);
                Vh32[off + 8 * 32]  = h2_rn(v2, v3);
            }
        }
    }
}

// ---------------------------------------------------------------------------
// Kernel 3: flash attention, fp16 mma.sync (FA2-style, P kept in registers).
// CTA: 128q x 64kv/iter, 8 warps x 16q. Rows padded to 144B (conflict-free
// LDSM). K/V double-buffered with register prefetch, one sync per iter.
// ---------------------------------------------------------------------------
#define AQ_OFF   0
#define AK_OFF   18432              /* + buf*18432 */
#define AV_OFF   (18432 + 9216)
#define ATTN_SMEM (18432 * 3)       /* 55296 B */

__global__ __launch_bounds__(256) void attn_kernel() {
    extern __shared__ char smc[];
    const uint32_t smb = smem_u32(smc);

    const int tid = threadIdx.x;
    const int lane = tid & 31;
    const int w = tid >> 5;
    const int g = lane >> 2, tg = lane & 3;
    const int bh = blockIdx.y;
    const int q0 = blockIdx.x * 128;

    const __half* Qg = g_Qh + ((size_t)bh * 2048 + q0) * 64;
    const __half* Kg = g_Kh + (size_t)bh * 2048 * 64;
    const __half* Vg = g_Vh + (size_t)bh * 2048 * 64;

    // ---- load Q tile (128 rows x 64 halves) into padded smem ----
    {
        int r = tid >> 1, hb = (tid & 1) * 32;     // row, half-offset
        #pragma unroll
        for (int i = 0; i < 4; i++)
            *(uint4*)(smc + r * 144 + hb * 2 + i * 16) =
                *(const uint4*)(Qg + (size_t)r * 64 + hb + i * 8);
    }

    // ---- K/V producer mapping: tids 0-127 -> K, 128-255 -> V ----
    const bool isV = (tid >= 128);
    const int pk = tid & 127;
    const int prow = pk >> 1;
    const int phb = (pk & 1) * 32;                  // half offset in row
    const __half* skv = isV ? Vg : Kg;
    const uint32_t soff = (isV ? (uint32_t)AV_OFF : (uint32_t)AK_OFF)
                        + (uint32_t)prow * 144u + (uint32_t)phb * 2u;

    uint4 pf[4];
    #pragma unroll
    for (int i = 0; i < 4; i++)
        pf[i] = *(const uint4*)(skv + (size_t)prow * 64 + phb + i * 8);
    #pragma unroll
    for (int i = 0; i < 4; i++)
        *(uint4*)(smc + soff + i * 16) = pf[i];
    __syncthreads();                                // Q + buf0 visible

    // ---- Q fragments (held in regs for whole loop) ----
    uint32_t qf[4][4];
    {
        uint32_t qa = smb + (uint32_t)((w * 16 + (lane & 15)) * 144)
                    + (uint32_t)(((lane >> 4) & 1) * 16);
        #pragma unroll
        for (int ks = 0; ks < 4; ks++) ldsm4(qf[ks], qa + ks * 32);
    }

    float out[8][4];
    #pragma unroll
    for (int n = 0; n < 8; n++)
        #pragma unroll
        for (int r = 0; r < 4; r++) out[n][r] = 0.f;
    float mi0 = -1e30f, mi1 = -1e30f, li0 = 0.f, li1 = 0.f;

    const uint32_t krow = (uint32_t)(((lane >> 4) & 1) * 8 + (lane & 7));
    const uint32_t kcol = (uint32_t)(((lane >> 3) & 1) * 16);
    const uint32_t vrow = (uint32_t)(((lane >> 3) & 1) * 8 + (lane & 7));
    const uint32_t vcol = (uint32_t)(((lane >> 4) & 1) * 16);

    for (int kt = 0; kt < 32; kt++) {
        const uint32_t kb = smb + (uint32_t)AK_OFF + (uint32_t)(kt & 1) * 18432u;
        const uint32_t vb = smb + (uint32_t)AV_OFF + (uint32_t)(kt & 1) * 18432u;

        if (kt < 31) {   // prefetch next K/V tile (hidden under MMAs)
            const __half* s2 = skv + (size_t)((kt + 1) * 64 + prow) * 64 + phb;
            #pragma unroll
            for (int i = 0; i < 4; i++) pf[i] = *(const uint4*)(s2 + i * 8);
        }

        // ---- S = Q K^T : 8 n-tiles (64 kv) ----
        float s[8][4];
        #pragma unroll
        for (int n = 0; n < 8; n++)
            #pragma unroll
            for (int r = 0; r < 4; r++) s[n][r] = 0.f;

        #pragma unroll
        for (int ks = 0; ks < 4; ks++) {
            #pragma unroll
            for (int p = 0; p < 4; p++) {
                uint32_t kf[4];
                ldsm4(kf, kb + (uint32_t)(p * 16) * 144u + krow * 144u
                          + (uint32_t)(ks * 32) + kcol);
                mma_f16(s[2*p],     qf[ks][0], qf[ks][1], qf[ks][2], qf[ks][3],
                        kf[0], kf[1]);
                mma_f16(s[2*p + 1], qf[ks][0], qf[ks][1], qf[ks][2], qf[ks][3],
                        kf[2], kf[3]);
            }
        }

        // ---- online softmax (rows g and g+8; row lives in a 4-lane group) ----
        float mx0 = s[0][0], mx1 = s[0][2];
        #pragma unroll
        for (int n = 0; n < 8; n++) {
            mx0 = fmaxf(mx0, fmaxf(s[n][0], s[n][1]));
            mx1 = fmaxf(mx1, fmaxf(s[n][2], s[n][3]));
        }
        mx0 = fmaxf(mx0, __shfl_xor_sync(0xffffffffu, mx0, 1));
        mx0 = fmaxf(mx0, __shfl_xor_sync(0xffffffffu, mx0, 2));
        mx1 = fmaxf(mx1, __shfl_xor_sync(0xffffffffu, mx1, 1));
        mx1 = fmaxf(mx1, __shfl_xor_sync(0xffffffffu, mx1, 2));

        float mn0 = fmaxf(mi0, mx0), mn1 = fmaxf(mi1, mx1);
        float a0 = __expf(mi0 - mn0), a1 = __expf(mi1 - mn1);
        mi0 = mn0; mi1 = mn1;

        float rs0 = 0.f, rs1 = 0.f;
        #pragma unroll
        for (int n = 0; n < 8; n++) {
            s[n][0] = __expf(s[n][0] - mn0); rs0 += s[n][0];
            s[n][1] = __expf(s[n][1] - mn0); rs0 += s[n][1];
            s[n][2] = __expf(s[n][2] - mn1); rs1 += s[n][2];
            s[n][3] = __expf(s[n][3] - mn1); rs1 += s[n][3];
        }
        rs0 += __shfl_xor_sync(0xffffffffu, rs0, 1);
        rs0 += __shfl_xor_sync(0xffffffffu, rs0, 2);
        rs1 += __shfl_xor_sync(0xffffffffu, rs1, 1);
        rs1 += __shfl_xor_sync(0xffffffffu, rs1, 2);
        li0 = li0 * a0 + rs0;
        li1 = li1 * a1 + rs1;

        #pragma unroll
        for (int n = 0; n < 8; n++) {
            out[n][0] *= a0; out[n][1] *= a0;
            out[n][2] *= a1; out[n][3] *= a1;
        }

        // ---- O += P V  (P frags formed in registers) ----
        #pragma unroll
        for (int ks = 0; ks < 4; ks++) {
            uint32_t af0 = h2_rn(s[2*ks][0],     s[2*ks][1]);
            uint32_t af1 = h2_rn(s[2*ks][2],     s[2*ks][3]);
            uint32_t af2 = h2_rn(s[2*ks + 1][0], s[2*ks + 1][1]);
            uint32_t af3 = h2_rn(s[2*ks + 1][2], s[2*ks + 1][3]);
            #pragma unroll
            for (int p = 0; p < 4; p++) {
                uint32_t vf[4];
                ldsm4t(vf, vb + (uint32_t)(ks * 16) * 144u + vrow * 144u
                           + (uint32_t)(p * 32) + vcol);
                mma_f16(out[2*p],     af0, af1, af2, af3, vf[0], vf[1]);
                mma_f16(out[2*p + 1], af0, af1, af2, af3, vf[2], vf[3]);
            }
        }

        if (kt < 31) {
            uint32_t dsoff = soff + (uint32_t)((kt + 1) & 1) * 18432u;
            // soff already contains buf0 base; strip and re-add:
            uint32_t base = soff - (uint32_t)0;   // buf0 layout; add delta only
            (void)base;
            #pragma unroll
            for (int i = 0; i < 4; i++)
                *(uint4*)(smc + ((kt & 1) ? soff : soff + 18432u) + i * 16) = pf[i];
            (void)dsoff;
        }
        __syncthreads();
    }

    // ---- epilogue: normalize, write g_A[b*T+t][h*64+d] ----
    const int b = bh >> 4, h = bh & 15;
    const float inv0 = 1.0f / li0, inv1 = 1.0f / li1;
    const int qr = q0 + w * 16 + g;
    #pragma unroll
    for (int n = 0; n < 8; n++) {
        int col = h * 64 + n * 8 + 2 * tg;
        *(float2*)&g_A[(size_t)(b * 2048 + qr) * 1024 + col] =
            make_float2(out[n][0] * inv0, out[n][1] * inv0);
        *(float2*)&g_A[(size_t)(b * 2048 + qr + 8) * 1024 + col] =
            make_float2(out[n][2] * inv1, out[n][3] * inv1);
    }
}

// ---------------------------------------------------------------------------
// Launcher
// ---------------------------------------------------------------------------
extern "C" void kernel_launch(void* const* d_in, const int* in_sizes, int n_in,
                              void* d_out, int out_size) {
    (void)in_sizes; (void)n_in; (void)out_size;
    const float* query = (const float*)d_in[0];
    const float* w_in  = (const float*)d_in[1];
    const float* b_in  = (const float*)d_in[2];
    const float* w_out = (const float*)d_in[3];
    const float* b_out = (const float*)d_in[4];
    float* out = (float*)d_out;

    void* pA = nullptr;
    cudaGetSymbolAddress(&pA, g_A);
    cudaFuncSetAttribute(attn_kernel,
                         cudaFuncAttributeMaxDynamicSharedMemorySize, ATTN_SMEM);
    cudaFuncSetAttribute(gemm_tc_kernel,
                         cudaFuncAttributeMaxDynamicSharedMemorySize, GEMM_SMEM);

    rope_table_kernel<<<(TT * 32 + 255) / 256, 256>>>();

    // QKV projection with fused bias + RoPE + fp16 scatter epilogue
    gemm_tc_kernel<<<dim3(N3 / 128, MM / 128), 256, GEMM_SMEM>>>(
        query, w_in, b_in, nullptr, N3, 1);

    attn_kernel<<<dim3(TT / 128, NBH), 256, ATTN_SMEM>>>();

    // output projection
    gemm_tc_kernel<<<dim3(DD / 128, MM / 128), 256, GEMM_SMEM>>>(
        (const float*)pA, w_out, b_out, out, DD, 0);
}